// round 15
// baseline (speedup 1.0000x reference)
#include <cuda_runtime.h>
#include <cuda_fp16.h>
#include <cstdint>

// ---------------------------------------------------------------------------
// AttentionLayer: B=2, S1=S2=2048, D=1024, H=16, dh=64
// out layout: [ output (2*2048*1024) | attn_weights (2*16*2048*2048) ] fp32
// mma.sync m16n8k16 (f16, f32 acc), fp16 hi/lo split (3 passes), 4-stage
// cp.async pipeline, merged QKV projection launch, fused exp-softmax + PV norm.
// ---------------------------------------------------------------------------

#define BATCH 2
#define SEQ   2048
#define DEMB  1024
#define NHEAD 16
#define DHEAD 64

#define QKV_ELEMS (BATCH * SEQ * DEMB)          // 4,194,304
#define NROWS     (BATCH * NHEAD * SEQ)         // 65,536
#define ATTN_OFF  ((size_t)BATCH * SEQ * DEMB)

__device__ float g_Q [QKV_ELEMS];
__device__ float g_K [QKV_ELEMS];
__device__ float g_Vt[QKV_ELEMS];   // [(b*1024 + h*64 + d)][s]
__device__ float g_AO[QKV_ELEMS];
__device__ float g_partial[16 * NROWS];
__device__ float g_inv[NROWS];

// ---------------------------------------------------------------------------
__device__ __forceinline__ void cpasync16(void* dst_smem, const void* src_gmem) {
    uint32_t d = (uint32_t)__cvta_generic_to_shared(dst_smem);
    asm volatile("cp.async.cg.shared.global [%0], [%1], 16;\n" :: "r"(d), "l"(src_gmem));
}
#define CP_COMMIT()  asm volatile("cp.async.commit_group;\n" ::: "memory")
#define CP_WAIT2()   asm volatile("cp.async.wait_group 2;\n" ::: "memory")

__device__ __forceinline__ void cvt2(float2 f, uint32_t& hi, uint32_t& lo) {
    __half2 h = __floats2half2_rn(f.x, f.y);
    float2 hf = __half22float2(h);
    __half2 l = __floats2half2_rn(f.x - hf.x, f.y - hf.y);
    hi = *reinterpret_cast<uint32_t*>(&h);
    lo = *reinterpret_cast<uint32_t*>(&l);
}
__device__ __forceinline__ void mma16816(float* c, const uint32_t* a, const uint32_t* b) {
    asm volatile(
        "mma.sync.aligned.m16n8k16.row.col.f32.f16.f16.f32 "
        "{%0,%1,%2,%3}, {%4,%5,%6,%7}, {%8,%9}, {%0,%1,%2,%3};\n"
        : "+f"(c[0]), "+f"(c[1]), "+f"(c[2]), "+f"(c[3])
        : "r"(a[0]), "r"(a[1]), "r"(a[2]), "r"(a[3]), "r"(b[0]), "r"(b[1]));
}

// ---------------------------------------------------------------------------
// Fragment load + 3-pass MMA body (shared by all kernels).
// sA/sB tiles are [rows][20] fp32, padded stride.
// ---------------------------------------------------------------------------
template <int NT>
__device__ __forceinline__ void compute_iter(
    const float (*sAst)[20], const float (*sBst)[20],
    int wm, int wn, int grp, int qid, float acc[][NT][4])
{
    uint32_t aH[4][4], aL[4][4];
#pragma unroll
    for (int mt = 0; mt < 4; mt++) {
        const int r0 = wm + mt * 16 + grp;
        float2 f00 = *reinterpret_cast<const float2*>(&sAst[r0    ][qid * 2    ]);
        float2 f10 = *reinterpret_cast<const float2*>(&sAst[r0 + 8][qid * 2    ]);
        float2 f01 = *reinterpret_cast<const float2*>(&sAst[r0    ][qid * 2 + 8]);
        float2 f11 = *reinterpret_cast<const float2*>(&sAst[r0 + 8][qid * 2 + 8]);
        cvt2(f00, aH[mt][0], aL[mt][0]);
        cvt2(f10, aH[mt][1], aL[mt][1]);
        cvt2(f01, aH[mt][2], aL[mt][2]);
        cvt2(f11, aH[mt][3], aL[mt][3]);
    }
    uint32_t bH[NT][2], bL[NT][2];
#pragma unroll
    for (int nt = 0; nt < NT; nt++) {
        const int c0 = wn + nt * 8 + grp;
        float2 g0 = *reinterpret_cast<const float2*>(&sBst[c0][qid * 2    ]);
        float2 g1 = *reinterpret_cast<const float2*>(&sBst[c0][qid * 2 + 8]);
        cvt2(g0, bH[nt][0], bL[nt][0]);
        cvt2(g1, bH[nt][1], bL[nt][1]);
    }
#pragma unroll
    for (int mt = 0; mt < 4; mt++)
#pragma unroll
        for (int nt = 0; nt < NT; nt++) {
            mma16816(acc[mt][nt], aH[mt], bH[nt]);
            mma16816(acc[mt][nt], aH[mt], bL[nt]);
            mma16816(acc[mt][nt], aL[mt], bH[nt]);
        }
}

// ---------------------------------------------------------------------------
// gemm_mma: 4-stage pipeline. C[m,n] = f(scale*sum A[m,k]B[n,k] (+bias))
// OUTMODE 0: fp32 out. OUTMODE 2: exp(scale*acc) + partial row sums.
// Requires K >= 48 (NKB >= 3). Dynamic smem.
// ---------------------------------------------------------------------------
template <int BN, int OUTMODE>
__global__ void __launch_bounds__(256)
gemm_mma(const float* __restrict__ A, const float* __restrict__ B,
         const float* __restrict__ bias, float* __restrict__ C,
         float* __restrict__ partial,
         int K, int lda, int ldb, int ldc,
         size_t aOffB, size_t aOffH,
         size_t bOffB, size_t bOffH,
         size_t cOffB, size_t cOffH,
         float scale)
{
    constexpr int NT = BN / 32;
    extern __shared__ float dsm[];
    float (*sA)[128][20] = reinterpret_cast<float(*)[128][20]>(dsm);
    float (*sB)[BN][20]  = reinterpret_cast<float(*)[BN][20]>(dsm + 4 * 128 * 20);
    float (*sred)[128]   = reinterpret_cast<float(*)[128]>(dsm + 4 * 128 * 20 + 4 * BN * 20);

    const int tid  = threadIdx.x;
    const int wid  = tid >> 5;
    const int lane = tid & 31;
    const int grp  = lane >> 2;
    const int qid  = lane & 3;
    const int wm   = (wid >> 2) * 64;
    const int wn   = (wid & 3) * (BN / 4);

    const int z    = blockIdx.z;
    const int bidx = z >> 4;
    const int h    = z & 15;
    A += (size_t)bidx * aOffB + (size_t)h * aOffH;
    B += (size_t)bidx * bOffB + (size_t)h * bOffH;
    float* Cb = C + (size_t)bidx * cOffB + (size_t)h * cOffH;

    const int m0 = blockIdx.y * 128;
    const int n0 = blockIdx.x * BN;
    const float* Ab = A + (size_t)m0 * lda;
    const float* Bb = B + (size_t)n0 * ldb;

    float acc[4][NT][4];
#pragma unroll
    for (int mt = 0; mt < 4; mt++)
#pragma unroll
        for (int nt = 0; nt < NT; nt++)
#pragma unroll
            for (int i = 0; i < 4; i++) acc[mt][nt][i] = 0.f;

    const int NKB = K >> 4;

    auto load_stage = [&](int st, int k0) {
#pragma unroll 2
        for (int i = tid; i < 128 * 4; i += 256) {
            const int r = i >> 2, sgm = i & 3;
            cpasync16(&sA[st][r][sgm * 4], Ab + (size_t)r * lda + k0 + sgm * 4);
        }
#pragma unroll 1
        for (int i = tid; i < BN * 4; i += 256) {
            const int r = i >> 2, sgm = i & 3;
            cpasync16(&sB[st][r][sgm * 4], Bb + (size_t)r * ldb + k0 + sgm * 4);
        }
    };

    load_stage(0, 0);  CP_COMMIT();
    load_stage(1, 16); CP_COMMIT();
    load_stage(2, 32); CP_COMMIT();

    for (int kb = 0; kb < NKB; kb++) {
        CP_WAIT2();
        __syncthreads();
        if (kb + 3 < NKB) load_stage((kb + 3) & 3, (kb + 3) << 4);
        CP_COMMIT();
        compute_iter<NT>(sA[kb & 3], sB[kb & 3], wm, wn, grp, qid, acc);
    }

    // ---------------- epilogue ----------------
    if (OUTMODE == 2) {
        float rs0[4] = {0.f, 0.f, 0.f, 0.f};
        float rs1[4] = {0.f, 0.f, 0.f, 0.f};
#pragma unroll
        for (int mt = 0; mt < 4; mt++) {
#pragma unroll
            for (int nt = 0; nt < NT; nt++) {
                const float* cc = acc[mt][nt];
                const int row = m0 + wm + mt * 16 + grp;
                const int col = n0 + wn + nt * 8 + qid * 2;
                float e00 = __expf(cc[0] * scale);
                float e01 = __expf(cc[1] * scale);
                float e10 = __expf(cc[2] * scale);
                float e11 = __expf(cc[3] * scale);
                rs0[mt] += e00 + e01;
                rs1[mt] += e10 + e11;
                *reinterpret_cast<float2*>(&Cb[(size_t)row * ldc + col]) = make_float2(e00, e01);
                *reinterpret_cast<float2*>(&Cb[(size_t)(row + 8) * ldc + col]) = make_float2(e10, e11);
            }
        }
#pragma unroll
        for (int mt = 0; mt < 4; mt++) {
            float s0 = rs0[mt], s1 = rs1[mt];
            s0 += __shfl_xor_sync(0xffffffffu, s0, 1);
            s0 += __shfl_xor_sync(0xffffffffu, s0, 2);
            s1 += __shfl_xor_sync(0xffffffffu, s1, 1);
            s1 += __shfl_xor_sync(0xffffffffu, s1, 2);
            if (qid == 0) {
                sred[wid & 3][wm + mt * 16 + grp]     = s0;
                sred[wid & 3][wm + mt * 16 + grp + 8] = s1;
            }
        }
        __syncthreads();
        if (tid < 128) {
            float p = sred[0][tid] + sred[1][tid] + sred[2][tid] + sred[3][tid];
            partial[(size_t)blockIdx.x * NROWS + (size_t)z * SEQ + m0 + tid] = p;
        }
        return;
    }

#pragma unroll
    for (int mt = 0; mt < 4; mt++) {
#pragma unroll
        for (int nt = 0; nt < NT; nt++) {
            const float* cc = acc[mt][nt];
            const int row = m0 + wm + mt * 16 + grp;
            const int col = n0 + wn + nt * 8 + qid * 2;
            float b0 = bias ? bias[col]     : 0.f;
            float b1 = bias ? bias[col + 1] : 0.f;
            *reinterpret_cast<float2*>(&Cb[(size_t)row * ldc + col]) =
                make_float2(cc[0] * scale + b0, cc[1] * scale + b1);
            *reinterpret_cast<float2*>(&Cb[(size_t)(row + 8) * ldc + col]) =
                make_float2(cc[2] * scale + b0, cc[3] * scale + b1);
        }
    }
}

// ---------------------------------------------------------------------------
// proj_qkv: merged Q/K/V projections. grid = (8, 32, 3); z selects projection.
// z=0: Q = x1@Wq^T+bq ; z=1: K = x2@Wk^T+bk ; z=2: Vt (transposed) = x2@Wv^T+bv
// ---------------------------------------------------------------------------
__global__ void __launch_bounds__(256)
proj_qkv(const float* __restrict__ x1, const float* __restrict__ x2,
         const float* __restrict__ Wq, const float* __restrict__ Wk,
         const float* __restrict__ Wv,
         const float* __restrict__ bq, const float* __restrict__ bk,
         const float* __restrict__ bv,
         float* __restrict__ Qo, float* __restrict__ Ko, float* __restrict__ Vt)
{
    constexpr int BN = 128;
    constexpr int NT = 4;
    extern __shared__ float dsm[];
    float (*sA)[128][20] = reinterpret_cast<float(*)[128][20]>(dsm);
    float (*sB)[BN][20]  = reinterpret_cast<float(*)[BN][20]>(dsm + 4 * 128 * 20);

    const int pz = blockIdx.z;
    const float* A    = (pz == 0) ? x1 : x2;
    const float* B    = (pz == 0) ? Wq : (pz == 1 ? Wk : Wv);
    const float* bias = (pz == 0) ? bq : (pz == 1 ? bk : bv);

    const int tid  = threadIdx.x;
    const int wid  = tid >> 5;
    const int lane = tid & 31;
    const int grp  = lane >> 2;
    const int qid  = lane & 3;
    const int wm   = (wid >> 2) * 64;
    const int wn   = (wid & 3) * 32;

    const int m0 = blockIdx.y * 128;
    const int n0 = blockIdx.x * BN;
    const float* Ab = A + (size_t)m0 * DEMB;
    const float* Bb = B + (size_t)n0 * DEMB;

    float acc[4][NT][4];
#pragma unroll
    for (int mt = 0; mt < 4; mt++)
#pragma unroll
        for (int nt = 0; nt < NT; nt++)
#pragma unroll
            for (int i = 0; i < 4; i++) acc[mt][nt][i] = 0.f;

    const int NKB = DEMB >> 4;  // 64

    auto load_stage = [&](int st, int k0) {
#pragma unroll 2
        for (int i = tid; i < 128 * 4; i += 256) {
            const int r = i >> 2, sgm = i & 3;
            cpasync16(&sA[st][r][sgm * 4], Ab + (size_t)r * DEMB + k0 + sgm * 4);
        }
#pragma unroll 2
        for (int i = tid; i < BN * 4; i += 256) {
            const int r = i >> 2, sgm = i & 3;
            cpasync16(&sB[st][r][sgm * 4], Bb + (size_t)r * DEMB + k0 + sgm * 4);
        }
    };

    load_stage(0, 0);  CP_COMMIT();
    load_stage(1, 16); CP_COMMIT();
    load_stage(2, 32); CP_COMMIT();

    for (int kb = 0; kb < NKB; kb++) {
        CP_WAIT2();
        __syncthreads();
        if (kb + 3 < NKB) load_stage((kb + 3) & 3, (kb + 3) << 4);
        CP_COMMIT();
        compute_iter<NT>(sA[kb & 3], sB[kb & 3], wm, wn, grp, qid, acc);
    }

    // epilogue
    if (pz < 2) {
        float* C = pz ? Ko : Qo;
#pragma unroll
        for (int mt = 0; mt < 4; mt++) {
#pragma unroll
            for (int nt = 0; nt < NT; nt++) {
                const float* cc = acc[mt][nt];
                const int row = m0 + wm + mt * 16 + grp;
                const int col = n0 + wn + nt * 8 + qid * 2;
                const float b0 = bias[col], b1 = bias[col + 1];
                *reinterpret_cast<float2*>(&C[(size_t)row * DEMB + col]) =
                    make_float2(cc[0] + b0, cc[1] + b1);
                *reinterpret_cast<float2*>(&C[(size_t)(row + 8) * DEMB + col]) =
                    make_float2(cc[2] + b0, cc[3] + b1);
            }
        }
    } else {
#pragma unroll
        for (int mt = 0; mt < 4; mt++) {
#pragma unroll
            for (int nt = 0; nt < NT; nt++) {
                const float* cc = acc[mt][nt];
                const int row = m0 + wm + mt * 16 + grp;
                const int col = n0 + wn + nt * 8 + qid * 2;
                const float b0 = bias[col], b1 = bias[col + 1];
                const int b2 = row >> 11;
                const int s  = row & 2047;
                Vt[((size_t)(b2 * 1024 + col    )) * 2048 + s]     = cc[0] + b0;
                Vt[((size_t)(b2 * 1024 + col + 1)) * 2048 + s]     = cc[1] + b1;
                Vt[((size_t)(b2 * 1024 + col    )) * 2048 + s + 8] = cc[2] + b0;
                Vt[((size_t)(b2 * 1024 + col + 1)) * 2048 + s + 8] = cc[3] + b1;
            }
        }
    }
}

// ---------------------------------------------------------------------------
__global__ void reduce_inv(const float* __restrict__ partial, float* __restrict__ inv)
{
    const int r = blockIdx.x * blockDim.x + threadIdx.x;
    if (r >= NROWS) return;
    float s = 0.f;
#pragma unroll
    for (int b = 0; b < 16; b++) s += partial[(size_t)b * NROWS + r];
    inv[r] = 1.f / s;
}

// ---------------------------------------------------------------------------
// gemm_pv: AO = inv[m] * (P @ Vt^T); P normalized in place. 4-stage pipeline.
// ---------------------------------------------------------------------------
__global__ void __launch_bounds__(256)
gemm_pv(float* __restrict__ Pmat, const float* __restrict__ Bm,
        const float* __restrict__ inv, float* __restrict__ Cm,
        int K, int lda, int ldb, int ldc,
        size_t aOffB, size_t aOffH,
        size_t bOffB, size_t bOffH,
        size_t cOffB, size_t cOffH)
{
    constexpr int BN = 64;
    constexpr int NT = 2;
    extern __shared__ float dsm[];
    float (*sA)[128][20] = reinterpret_cast<float(*)[128][20]>(dsm);
    float (*sB)[BN][20]  = reinterpret_cast<float(*)[BN][20]>(dsm + 4 * 128 * 20);

    const int tid  = threadIdx.x;
    const int wid  = tid >> 5;
    const int lane = tid & 31;
    const int grp  = lane >> 2;
    const int qid  = lane & 3;
    const int wm   = (wid >> 2) * 64;
    const int wn   = (wid & 3) * 16;

    const int z    = blockIdx.z;
    const int bidx = z >> 4;
    const int h    = z & 15;
    float* Ap = Pmat + (size_t)bidx * aOffB + (size_t)h * aOffH;
    const float* Bp = Bm + (size_t)bidx * bOffB + (size_t)h * bOffH;
    float* Cb = Cm + (size_t)bidx * cOffB + (size_t)h * cOffH;

    const int m0 = blockIdx.y * 128;
    float* Ab = Ap + (size_t)m0 * lda;

    const int wbR = tid >> 1;
    const int wbC = (tid & 1) * 8;
    const float wbInv = inv[(size_t)z * SEQ + m0 + wbR];

    float acc[4][NT][4];
#pragma unroll
    for (int mt = 0; mt < 4; mt++)
#pragma unroll
        for (int nt = 0; nt < NT; nt++)
#pragma unroll
            for (int i = 0; i < 4; i++) acc[mt][nt][i] = 0.f;

    const int NKB = K >> 4;

    auto load_stage = [&](int st, int k0) {
#pragma unroll 2
        for (int i = tid; i < 128 * 4; i += 256) {
            const int r = i >> 2, sgm = i & 3;
            cpasync16(&sA[st][r][sgm * 4], Ab + (size_t)r * lda + k0 + sgm * 4);
        }
        if (tid < BN * 4) {
            const int r = tid >> 2, sgm = tid & 3;
            cpasync16(&sB[st][r][sgm * 4], Bp + (size_t)r * ldb + k0 + sgm * 4);
        }
    };

    load_stage(0, 0);  CP_COMMIT();
    load_stage(1, 16); CP_COMMIT();
    load_stage(2, 32); CP_COMMIT();

    for (int kb = 0; kb < NKB; kb++) {
        CP_WAIT2();
        __syncthreads();
        if (kb + 3 < NKB) load_stage((kb + 3) & 3, (kb + 3) << 4);
        CP_COMMIT();

        const int st = kb & 3;
        const int k0 = kb << 4;

        // normalized writeback of this P tile (final attn_weights)
        {
            float4 v0 = *reinterpret_cast<const float4*>(&sA[st][wbR][wbC]);
            float4 v1 = *reinterpret_cast<const float4*>(&sA[st][wbR][wbC + 4]);
            v0.x *= wbInv; v0.y *= wbInv; v0.z *= wbInv; v0.w *= wbInv;
            v1.x *= wbInv; v1.y *= wbInv; v1.z *= wbInv; v1.w *= wbInv;
            float* dst = Ab + (size_t)wbR * lda + k0 + wbC;
            *reinterpret_cast<float4*>(dst)     = v0;
            *reinterpret_cast<float4*>(dst + 4) = v1;
        }

        compute_iter<NT>(sA[st], sB[st], wm, wn, grp, qid, acc);
    }

#pragma unroll
    for (int mt = 0; mt < 4; mt++) {
        const int row = m0 + wm + mt * 16 + grp;
        const float i0 = inv[(size_t)z * SEQ + row];
        const float i1 = inv[(size_t)z * SEQ + row + 8];
#pragma unroll
        for (int nt = 0; nt < NT; nt++) {
            const float* cc = acc[mt][nt];
            const int col = wn + nt * 8 + qid * 2;
            *reinterpret_cast<float2*>(&Cb[(size_t)row * ldc + col]) =
                make_float2(cc[0] * i0, cc[1] * i0);
            *reinterpret_cast<float2*>(&Cb[(size_t)(row + 8) * ldc + col]) =
                make_float2(cc[2] * i1, cc[3] * i1);
        }
    }
}

// ---------------------------------------------------------------------------

extern "C" void kernel_launch(void* const* d_in, const int* in_sizes, int n_in,
                              void* d_out, int out_size)
{
    const float* x1 = (const float*)d_in[0];
    const float* x2 = (const float*)d_in[1];
    const float* Wq = (const float*)d_in[2];
    const float* bq = (const float*)d_in[3];
    const float* Wk = (const float*)d_in[4];
    const float* bk = (const float*)d_in[5];
    const float* Wv = (const float*)d_in[6];
    const float* bv = (const float*)d_in[7];
    const float* Wo = (const float*)d_in[8];
    const float* bo = (const float*)d_in[9];
    float* out = (float*)d_out;

    constexpr int SM_G128 = (4 * 128 * 20 + 4 * 128 * 20 + 4 * 128) * 4; // 83968
    constexpr int SM_PROJ = (4 * 128 * 20 + 4 * 128 * 20) * 4;           // 81920
    constexpr int SM_PV   = (4 * 128 * 20 + 4 * 64 * 20) * 4;            // 61440

    static float *Q = nullptr, *K = nullptr, *Vt = nullptr, *AO = nullptr,
                 *PART = nullptr, *INV = nullptr;
    if (Q == nullptr) {
        cudaGetSymbolAddress((void**)&Q,    g_Q);
        cudaGetSymbolAddress((void**)&K,    g_K);
        cudaGetSymbolAddress((void**)&Vt,   g_Vt);
        cudaGetSymbolAddress((void**)&AO,   g_AO);
        cudaGetSymbolAddress((void**)&PART, g_partial);
        cudaGetSymbolAddress((void**)&INV,  g_inv);
        cudaFuncSetAttribute(gemm_mma<128, 0>, cudaFuncAttributeMaxDynamicSharedMemorySize, SM_G128);
        cudaFuncSetAttribute(gemm_mma<128, 2>, cudaFuncAttributeMaxDynamicSharedMemorySize, SM_G128);
        cudaFuncSetAttribute(proj_qkv,          cudaFuncAttributeMaxDynamicSharedMemorySize, SM_PROJ);
        cudaFuncSetAttribute(gemm_pv,           cudaFuncAttributeMaxDynamicSharedMemorySize, SM_PV);
    }

    const size_t SD = (size_t)SEQ * DEMB;   // 2,097,152
    const size_t SS = (size_t)SEQ * SEQ;    // 4,194,304
    float* Pattn = out + ATTN_OFF;

    // 1) merged Q/K/V projections (one launch, z selects)
    {
        dim3 grid(DEMB / 128, (BATCH * SEQ) / 128, 3);
        proj_qkv<<<grid, 256, SM_PROJ>>>(x1, x2, Wq, Wk, Wv, bq, bk, bv, Q, K, Vt);
    }

    // 2) P = exp(Q K^T / 8) + partial row sums
    {
        dim3 grid(SEQ / 128, SEQ / 128, BATCH * NHEAD);
        gemm_mma<128, 2><<<grid, 256, SM_G128>>>(Q, K, nullptr, Pattn, PART,
            DHEAD, DEMB, DEMB, SEQ,
            SD, (size_t)DHEAD,
            SD, (size_t)DHEAD,
            (size_t)NHEAD * SS, SS,
            0.125f);
    }

    // 3) row-sum inverse
    reduce_inv<<<NROWS / 256, 256>>>(PART, INV);

    // 4) AO = inv * (P @ Vt^T); P normalized in place
    {
        dim3 grid(1, SEQ / 128, BATCH * NHEAD);
        gemm_pv<<<grid, 256, SM_PV>>>(Pattn, Vt, INV, AO,
            SEQ, SEQ, SEQ, DEMB,
            (size_t)NHEAD * SS, SS,
            (size_t)(NHEAD * DHEAD) * SEQ, (size_t)DHEAD * SEQ,
            SD, (size_t)DHEAD);
    }

    // 5) output = AO @ Wo^T + bo
    {
        dim3 grid(DEMB / 128, (BATCH * SEQ) / 128, 1);
        gemm_mma<128, 0><<<grid, 256, SM_G128>>>(AO, Wo, bo, out, nullptr,
            DEMB, DEMB, DEMB, DEMB, 0,0, 0,0, 0,0, 1.f);
    }
}

// round 16
// speedup vs baseline: 1.0445x; 1.0445x over previous
#include <cuda_runtime.h>
#include <cuda_fp16.h>
#include <cstdint>

// ---------------------------------------------------------------------------
// AttentionLayer: B=2, S1=S2=2048, D=1024, H=16, dh=64
// out layout: [ output (2*2048*1024) | attn_weights (2*16*2048*2048) ] fp32
// mma.sync m16n8k16 (f16, f32 acc), fp16 hi/lo split (3 passes), 4-stage
// cp.async pipeline, merged QKV projections, fused exp-softmax, split-K PV.
// ---------------------------------------------------------------------------

#define BATCH 2
#define SEQ   2048
#define DEMB  1024
#define NHEAD 16
#define DHEAD 64

#define QKV_ELEMS (BATCH * SEQ * DEMB)          // 4,194,304
#define NROWS     (BATCH * NHEAD * SEQ)         // 65,536
#define ATTN_OFF  ((size_t)BATCH * SEQ * DEMB)
#define KSPLIT    4
#define KSLICE    (SEQ / KSPLIT)                // 512

__device__ float g_Q [QKV_ELEMS];
__device__ float g_K [QKV_ELEMS];
__device__ float g_Vt[QKV_ELEMS];   // [(b*1024 + h*64 + d)][s]
__device__ float g_AO[QKV_ELEMS];
__device__ float g_AOpart[KSPLIT * QKV_ELEMS];
__device__ float g_partial[16 * NROWS];
__device__ float g_inv[NROWS];

// ---------------------------------------------------------------------------
__device__ __forceinline__ void cpasync16(void* dst_smem, const void* src_gmem) {
    uint32_t d = (uint32_t)__cvta_generic_to_shared(dst_smem);
    asm volatile("cp.async.cg.shared.global [%0], [%1], 16;\n" :: "r"(d), "l"(src_gmem));
}
#define CP_COMMIT()  asm volatile("cp.async.commit_group;\n" ::: "memory")
#define CP_WAIT2()   asm volatile("cp.async.wait_group 2;\n" ::: "memory")

__device__ __forceinline__ void cvt2(float2 f, uint32_t& hi, uint32_t& lo) {
    __half2 h = __floats2half2_rn(f.x, f.y);
    float2 hf = __half22float2(h);
    __half2 l = __floats2half2_rn(f.x - hf.x, f.y - hf.y);
    hi = *reinterpret_cast<uint32_t*>(&h);
    lo = *reinterpret_cast<uint32_t*>(&l);
}
__device__ __forceinline__ void mma16816(float* c, const uint32_t* a, const uint32_t* b) {
    asm volatile(
        "mma.sync.aligned.m16n8k16.row.col.f32.f16.f16.f32 "
        "{%0,%1,%2,%3}, {%4,%5,%6,%7}, {%8,%9}, {%0,%1,%2,%3};\n"
        : "+f"(c[0]), "+f"(c[1]), "+f"(c[2]), "+f"(c[3])
        : "r"(a[0]), "r"(a[1]), "r"(a[2]), "r"(a[3]), "r"(b[0]), "r"(b[1]));
}

// ---------------------------------------------------------------------------
template <int NT>
__device__ __forceinline__ void compute_iter(
    const float (*sAst)[20], const float (*sBst)[20],
    int wm, int wn, int grp, int qid, float acc[][NT][4])
{
    uint32_t aH[4][4], aL[4][4];
#pragma unroll
    for (int mt = 0; mt < 4; mt++) {
        const int r0 = wm + mt * 16 + grp;
        float2 f00 = *reinterpret_cast<const float2*>(&sAst[r0    ][qid * 2    ]);
        float2 f10 = *reinterpret_cast<const float2*>(&sAst[r0 + 8][qid * 2    ]);
        float2 f01 = *reinterpret_cast<const float2*>(&sAst[r0    ][qid * 2 + 8]);
        float2 f11 = *reinterpret_cast<const float2*>(&sAst[r0 + 8][qid * 2 + 8]);
        cvt2(f00, aH[mt][0], aL[mt][0]);
        cvt2(f10, aH[mt][1], aL[mt][1]);
        cvt2(f01, aH[mt][2], aL[mt][2]);
        cvt2(f11, aH[mt][3], aL[mt][3]);
    }
    uint32_t bH[NT][2], bL[NT][2];
#pragma unroll
    for (int nt = 0; nt < NT; nt++) {
        const int c0 = wn + nt * 8 + grp;
        float2 g0 = *reinterpret_cast<const float2*>(&sBst[c0][qid * 2    ]);
        float2 g1 = *reinterpret_cast<const float2*>(&sBst[c0][qid * 2 + 8]);
        cvt2(g0, bH[nt][0], bL[nt][0]);
        cvt2(g1, bH[nt][1], bL[nt][1]);
    }
#pragma unroll
    for (int mt = 0; mt < 4; mt++)
#pragma unroll
        for (int nt = 0; nt < NT; nt++) {
            mma16816(acc[mt][nt], aH[mt], bH[nt]);
            mma16816(acc[mt][nt], aH[mt], bL[nt]);
            mma16816(acc[mt][nt], aL[mt], bH[nt]);
        }
}

// ---------------------------------------------------------------------------
// gemm_mma: 4-stage pipeline. OUTMODE 0: fp32 out. OUTMODE 2: exp + partials.
// ---------------------------------------------------------------------------
template <int BN, int OUTMODE>
__global__ void __launch_bounds__(256)
gemm_mma(const float* __restrict__ A, const float* __restrict__ B,
         const float* __restrict__ bias, float* __restrict__ C,
         float* __restrict__ partial,
         int K, int lda, int ldb, int ldc,
         size_t aOffB, size_t aOffH,
         size_t bOffB, size_t bOffH,
         size_t cOffB, size_t cOffH,
         float scale)
{
    constexpr int NT = BN / 32;
    extern __shared__ float dsm[];
    float (*sA)[128][20] = reinterpret_cast<float(*)[128][20]>(dsm);
    float (*sB)[BN][20]  = reinterpret_cast<float(*)[BN][20]>(dsm + 4 * 128 * 20);
    float (*sred)[128]   = reinterpret_cast<float(*)[128]>(dsm + 4 * 128 * 20 + 4 * BN * 20);

    const int tid  = threadIdx.x;
    const int wid  = tid >> 5;
    const int lane = tid & 31;
    const int grp  = lane >> 2;
    const int qid  = lane & 3;
    const int wm   = (wid >> 2) * 64;
    const int wn   = (wid & 3) * (BN / 4);

    const int z    = blockIdx.z;
    const int bidx = z >> 4;
    const int h    = z & 15;
    A += (size_t)bidx * aOffB + (size_t)h * aOffH;
    B += (size_t)bidx * bOffB + (size_t)h * bOffH;
    float* Cb = C + (size_t)bidx * cOffB + (size_t)h * cOffH;

    const int m0 = blockIdx.y * 128;
    const int n0 = blockIdx.x * BN;
    const float* Ab = A + (size_t)m0 * lda;
    const float* Bb = B + (size_t)n0 * ldb;

    float acc[4][NT][4];
#pragma unroll
    for (int mt = 0; mt < 4; mt++)
#pragma unroll
        for (int nt = 0; nt < NT; nt++)
#pragma unroll
            for (int i = 0; i < 4; i++) acc[mt][nt][i] = 0.f;

    const int NKB = K >> 4;

    auto load_stage = [&](int st, int k0) {
#pragma unroll 2
        for (int i = tid; i < 128 * 4; i += 256) {
            const int r = i >> 2, sgm = i & 3;
            cpasync16(&sA[st][r][sgm * 4], Ab + (size_t)r * lda + k0 + sgm * 4);
        }
#pragma unroll 1
        for (int i = tid; i < BN * 4; i += 256) {
            const int r = i >> 2, sgm = i & 3;
            cpasync16(&sB[st][r][sgm * 4], Bb + (size_t)r * ldb + k0 + sgm * 4);
        }
    };

    load_stage(0, 0);  CP_COMMIT();
    load_stage(1, 16); CP_COMMIT();
    load_stage(2, 32); CP_COMMIT();

    for (int kb = 0; kb < NKB; kb++) {
        CP_WAIT2();
        __syncthreads();
        if (kb + 3 < NKB) load_stage((kb + 3) & 3, (kb + 3) << 4);
        CP_COMMIT();
        compute_iter<NT>(sA[kb & 3], sB[kb & 3], wm, wn, grp, qid, acc);
    }

    if (OUTMODE == 2) {
        float rs0[4] = {0.f, 0.f, 0.f, 0.f};
        float rs1[4] = {0.f, 0.f, 0.f, 0.f};
#pragma unroll
        for (int mt = 0; mt < 4; mt++) {
#pragma unroll
            for (int nt = 0; nt < NT; nt++) {
                const float* cc = acc[mt][nt];
                const int row = m0 + wm + mt * 16 + grp;
                const int col = n0 + wn + nt * 8 + qid * 2;
                float e00 = __expf(cc[0] * scale);
                float e01 = __expf(cc[1] * scale);
                float e10 = __expf(cc[2] * scale);
                float e11 = __expf(cc[3] * scale);
                rs0[mt] += e00 + e01;
                rs1[mt] += e10 + e11;
                __stcs(reinterpret_cast<float2*>(&Cb[(size_t)row * ldc + col]), make_float2(e00, e01));
                __stcs(reinterpret_cast<float2*>(&Cb[(size_t)(row + 8) * ldc + col]), make_float2(e10, e11));
            }
        }
#pragma unroll
        for (int mt = 0; mt < 4; mt++) {
            float s0 = rs0[mt], s1 = rs1[mt];
            s0 += __shfl_xor_sync(0xffffffffu, s0, 1);
            s0 += __shfl_xor_sync(0xffffffffu, s0, 2);
            s1 += __shfl_xor_sync(0xffffffffu, s1, 1);
            s1 += __shfl_xor_sync(0xffffffffu, s1, 2);
            if (qid == 0) {
                sred[wid & 3][wm + mt * 16 + grp]     = s0;
                sred[wid & 3][wm + mt * 16 + grp + 8] = s1;
            }
        }
        __syncthreads();
        if (tid < 128) {
            float p = sred[0][tid] + sred[1][tid] + sred[2][tid] + sred[3][tid];
            partial[(size_t)blockIdx.x * NROWS + (size_t)z * SEQ + m0 + tid] = p;
        }
        return;
    }

#pragma unroll
    for (int mt = 0; mt < 4; mt++) {
#pragma unroll
        for (int nt = 0; nt < NT; nt++) {
            const float* cc = acc[mt][nt];
            const int row = m0 + wm + mt * 16 + grp;
            const int col = n0 + wn + nt * 8 + qid * 2;
            float b0 = bias ? bias[col]     : 0.f;
            float b1 = bias ? bias[col + 1] : 0.f;
            *reinterpret_cast<float2*>(&Cb[(size_t)row * ldc + col]) =
                make_float2(cc[0] * scale + b0, cc[1] * scale + b1);
            *reinterpret_cast<float2*>(&Cb[(size_t)(row + 8) * ldc + col]) =
                make_float2(cc[2] * scale + b0, cc[3] * scale + b1);
        }
    }
}

// ---------------------------------------------------------------------------
// proj_qkv: merged Q/K/V projections. grid = (8, 32, 3); z selects projection.
// ---------------------------------------------------------------------------
__global__ void __launch_bounds__(256)
proj_qkv(const float* __restrict__ x1, const float* __restrict__ x2,
         const float* __restrict__ Wq, const float* __restrict__ Wk,
         const float* __restrict__ Wv,
         const float* __restrict__ bq, const float* __restrict__ bk,
         const float* __restrict__ bv,
         float* __restrict__ Qo, float* __restrict__ Ko, float* __restrict__ Vt)
{
    constexpr int BN = 128;
    constexpr int NT = 4;
    extern __shared__ float dsm[];
    float (*sA)[128][20] = reinterpret_cast<float(*)[128][20]>(dsm);
    float (*sB)[BN][20]  = reinterpret_cast<float(*)[BN][20]>(dsm + 4 * 128 * 20);

    const int pz = blockIdx.z;
    const float* A    = (pz == 0) ? x1 : x2;
    const float* B    = (pz == 0) ? Wq : (pz == 1 ? Wk : Wv);
    const float* bias = (pz == 0) ? bq : (pz == 1 ? bk : bv);

    const int tid  = threadIdx.x;
    const int wid  = tid >> 5;
    const int lane = tid & 31;
    const int grp  = lane >> 2;
    const int qid  = lane & 3;
    const int wm   = (wid >> 2) * 64;
    const int wn   = (wid & 3) * 32;

    const int m0 = blockIdx.y * 128;
    const int n0 = blockIdx.x * BN;
    const float* Ab = A + (size_t)m0 * DEMB;
    const float* Bb = B + (size_t)n0 * DEMB;

    float acc[4][NT][4];
#pragma unroll
    for (int mt = 0; mt < 4; mt++)
#pragma unroll
        for (int nt = 0; nt < NT; nt++)
#pragma unroll
            for (int i = 0; i < 4; i++) acc[mt][nt][i] = 0.f;

    const int NKB = DEMB >> 4;  // 64

    auto load_stage = [&](int st, int k0) {
#pragma unroll 2
        for (int i = tid; i < 128 * 4; i += 256) {
            const int r = i >> 2, sgm = i & 3;
            cpasync16(&sA[st][r][sgm * 4], Ab + (size_t)r * DEMB + k0 + sgm * 4);
        }
#pragma unroll 2
        for (int i = tid; i < BN * 4; i += 256) {
            const int r = i >> 2, sgm = i & 3;
            cpasync16(&sB[st][r][sgm * 4], Bb + (size_t)r * DEMB + k0 + sgm * 4);
        }
    };

    load_stage(0, 0);  CP_COMMIT();
    load_stage(1, 16); CP_COMMIT();
    load_stage(2, 32); CP_COMMIT();

    for (int kb = 0; kb < NKB; kb++) {
        CP_WAIT2();
        __syncthreads();
        if (kb + 3 < NKB) load_stage((kb + 3) & 3, (kb + 3) << 4);
        CP_COMMIT();
        compute_iter<NT>(sA[kb & 3], sB[kb & 3], wm, wn, grp, qid, acc);
    }

    if (pz < 2) {
        float* C = pz ? Ko : Qo;
#pragma unroll
        for (int mt = 0; mt < 4; mt++) {
#pragma unroll
            for (int nt = 0; nt < NT; nt++) {
                const float* cc = acc[mt][nt];
                const int row = m0 + wm + mt * 16 + grp;
                const int col = n0 + wn + nt * 8 + qid * 2;
                const float b0 = bias[col], b1 = bias[col + 1];
                *reinterpret_cast<float2*>(&C[(size_t)row * DEMB + col]) =
                    make_float2(cc[0] + b0, cc[1] + b1);
                *reinterpret_cast<float2*>(&C[(size_t)(row + 8) * DEMB + col]) =
                    make_float2(cc[2] + b0, cc[3] + b1);
            }
        }
    } else {
#pragma unroll
        for (int mt = 0; mt < 4; mt++) {
#pragma unroll
            for (int nt = 0; nt < NT; nt++) {
                const float* cc = acc[mt][nt];
                const int row = m0 + wm + mt * 16 + grp;
                const int col = n0 + wn + nt * 8 + qid * 2;
                const float b0 = bias[col], b1 = bias[col + 1];
                const int b2 = row >> 11;
                const int s  = row & 2047;
                Vt[((size_t)(b2 * 1024 + col    )) * 2048 + s]     = cc[0] + b0;
                Vt[((size_t)(b2 * 1024 + col + 1)) * 2048 + s]     = cc[1] + b1;
                Vt[((size_t)(b2 * 1024 + col    )) * 2048 + s + 8] = cc[2] + b0;
                Vt[((size_t)(b2 * 1024 + col + 1)) * 2048 + s + 8] = cc[3] + b1;
            }
        }
    }
}

// ---------------------------------------------------------------------------
__global__ void reduce_inv(const float* __restrict__ partial, float* __restrict__ inv)
{
    const int r = blockIdx.x * blockDim.x + threadIdx.x;
    if (r >= NROWS) return;
    float s = 0.f;
#pragma unroll
    for (int b = 0; b < 16; b++) s += partial[(size_t)b * NROWS + r];
    inv[r] = 1.f / s;
}

// ---------------------------------------------------------------------------
// gemm_pv split-K: grid (KSPLIT, 16, 32). Each block handles k-slice of 512:
// partial AO (inv-scaled) -> AOpart[ks]; normalizes its P k-range in place.
// ---------------------------------------------------------------------------
__global__ void __launch_bounds__(256)
gemm_pv(float* __restrict__ Pmat, const float* __restrict__ Bm,
        const float* __restrict__ inv, float* __restrict__ AOpart,
        int lda, int ldb, int ldc,
        size_t aOffB, size_t aOffH,
        size_t bOffB, size_t bOffH,
        size_t cOffB, size_t cOffH)
{
    constexpr int BN = 64;
    constexpr int NT = 2;
    extern __shared__ float dsm[];
    float (*sA)[128][20] = reinterpret_cast<float(*)[128][20]>(dsm);
    float (*sB)[BN][20]  = reinterpret_cast<float(*)[BN][20]>(dsm + 4 * 128 * 20);

    const int tid  = threadIdx.x;
    const int wid  = tid >> 5;
    const int lane = tid & 31;
    const int grp  = lane >> 2;
    const int qid  = lane & 3;
    const int wm   = (wid >> 2) * 64;
    const int wn   = (wid & 3) * 16;

    const int ks   = blockIdx.x;           // k-slice index
    const int z    = blockIdx.z;
    const int bidx = z >> 4;
    const int h    = z & 15;
    float* Ap = Pmat + (size_t)bidx * aOffB + (size_t)h * aOffH;
    const float* Bp = Bm + (size_t)bidx * bOffB + (size_t)h * bOffH + ks * KSLICE;
    float* Cb = AOpart + (size_t)ks * QKV_ELEMS
                       + (size_t)bidx * cOffB + (size_t)h * cOffH;

    const int m0 = blockIdx.y * 128;
    float* Ab = Ap + (size_t)m0 * lda + ks * KSLICE;

    const int wbR = tid >> 1;
    const int wbC = (tid & 1) * 8;
    const float wbInv = inv[(size_t)z * SEQ + m0 + wbR];

    float acc[4][NT][4];
#pragma unroll
    for (int mt = 0; mt < 4; mt++)
#pragma unroll
        for (int nt = 0; nt < NT; nt++)
#pragma unroll
            for (int i = 0; i < 4; i++) acc[mt][nt][i] = 0.f;

    const int NKB = KSLICE >> 4;   // 32

    auto load_stage = [&](int st, int k0) {
#pragma unroll 2
        for (int i = tid; i < 128 * 4; i += 256) {
            const int r = i >> 2, sgm = i & 3;
            cpasync16(&sA[st][r][sgm * 4], Ab + (size_t)r * lda + k0 + sgm * 4);
        }
        if (tid < BN * 4) {
            const int r = tid >> 2, sgm = tid & 3;
            cpasync16(&sB[st][r][sgm * 4], Bp + (size_t)r * ldb + k0 + sgm * 4);
        }
    };

    load_stage(0, 0);  CP_COMMIT();
    load_stage(1, 16); CP_COMMIT();
    load_stage(2, 32); CP_COMMIT();

    for (int kb = 0; kb < NKB; kb++) {
        CP_WAIT2();
        __syncthreads();
        if (kb + 3 < NKB) load_stage((kb + 3) & 3, (kb + 3) << 4);
        CP_COMMIT();

        const int st = kb & 3;
        const int k0 = kb << 4;

        // normalized writeback of this P tile (final attn_weights)
        {
            float4 v0 = *reinterpret_cast<const float4*>(&sA[st][wbR][wbC]);
            float4 v1 = *reinterpret_cast<const float4*>(&sA[st][wbR][wbC + 4]);
            v0.x *= wbInv; v0.y *= wbInv; v0.z *= wbInv; v0.w *= wbInv;
            v1.x *= wbInv; v1.y *= wbInv; v1.z *= wbInv; v1.w *= wbInv;
            float* dst = Ab + (size_t)wbR * lda + k0 + wbC;
            __stcs(reinterpret_cast<float4*>(dst), v0);
            __stcs(reinterpret_cast<float4*>(dst + 4), v1);
        }

        compute_iter<NT>(sA[st], sB[st], wm, wn, grp, qid, acc);
    }

#pragma unroll
    for (int mt = 0; mt < 4; mt++) {
        const int row = m0 + wm + mt * 16 + grp;
        const float i0 = inv[(size_t)z * SEQ + row];
        const float i1 = inv[(size_t)z * SEQ + row + 8];
#pragma unroll
        for (int nt = 0; nt < NT; nt++) {
            const float* cc = acc[mt][nt];
            const int col = wn + nt * 8 + qid * 2;
            *reinterpret_cast<float2*>(&Cb[(size_t)row * ldc + col]) =
                make_float2(cc[0] * i0, cc[1] * i0);
            *reinterpret_cast<float2*>(&Cb[(size_t)(row + 8) * ldc + col]) =
                make_float2(cc[2] * i1, cc[3] * i1);
        }
    }
}

// ---------------------------------------------------------------------------
// reduce_ao: AO[i] = sum over KSPLIT scaled partials (float4 vectorized)
// ---------------------------------------------------------------------------
__global__ void reduce_ao(const float* __restrict__ part, float* __restrict__ AO)
{
    const int i = blockIdx.x * blockDim.x + threadIdx.x;   // float4 index
    if (i >= QKV_ELEMS / 4) return;
    float4 s = reinterpret_cast<const float4*>(part)[i];
#pragma unroll
    for (int b = 1; b < KSPLIT; b++) {
        float4 v = reinterpret_cast<const float4*>(part + (size_t)b * QKV_ELEMS)[i];
        s.x += v.x; s.y += v.y; s.z += v.z; s.w += v.w;
    }
    reinterpret_cast<float4*>(AO)[i] = s;
}

// ---------------------------------------------------------------------------

extern "C" void kernel_launch(void* const* d_in, const int* in_sizes, int n_in,
                              void* d_out, int out_size)
{
    const float* x1 = (const float*)d_in[0];
    const float* x2 = (const float*)d_in[1];
    const float* Wq = (const float*)d_in[2];
    const float* bq = (const float*)d_in[3];
    const float* Wk = (const float*)d_in[4];
    const float* bk = (const float*)d_in[5];
    const float* Wv = (const float*)d_in[6];
    const float* bv = (const float*)d_in[7];
    const float* Wo = (const float*)d_in[8];
    const float* bo = (const float*)d_in[9];
    float* out = (float*)d_out;

    constexpr int SM_G128 = (4 * 128 * 20 + 4 * 128 * 20 + 4 * 128) * 4; // 83968
    constexpr int SM_PROJ = (4 * 128 * 20 + 4 * 128 * 20) * 4;           // 81920
    constexpr int SM_PV   = (4 * 128 * 20 + 4 * 64 * 20) * 4;            // 61440

    static float *Q = nullptr, *K = nullptr, *Vt = nullptr, *AO = nullptr,
                 *AOP = nullptr, *PART = nullptr, *INV = nullptr;
    if (Q == nullptr) {
        cudaGetSymbolAddress((void**)&Q,    g_Q);
        cudaGetSymbolAddress((void**)&K,    g_K);
        cudaGetSymbolAddress((void**)&Vt,   g_Vt);
        cudaGetSymbolAddress((void**)&AO,   g_AO);
        cudaGetSymbolAddress((void**)&AOP,  g_AOpart);
        cudaGetSymbolAddress((void**)&PART, g_partial);
        cudaGetSymbolAddress((void**)&INV,  g_inv);
        cudaFuncSetAttribute(gemm_mma<128, 0>, cudaFuncAttributeMaxDynamicSharedMemorySize, SM_G128);
        cudaFuncSetAttribute(gemm_mma<128, 2>, cudaFuncAttributeMaxDynamicSharedMemorySize, SM_G128);
        cudaFuncSetAttribute(proj_qkv,          cudaFuncAttributeMaxDynamicSharedMemorySize, SM_PROJ);
        cudaFuncSetAttribute(gemm_pv,           cudaFuncAttributeMaxDynamicSharedMemorySize, SM_PV);
    }

    const size_t SD = (size_t)SEQ * DEMB;   // 2,097,152
    const size_t SS = (size_t)SEQ * SEQ;    // 4,194,304
    float* Pattn = out + ATTN_OFF;

    // 1) merged Q/K/V projections
    {
        dim3 grid(DEMB / 128, (BATCH * SEQ) / 128, 3);
        proj_qkv<<<grid, 256, SM_PROJ>>>(x1, x2, Wq, Wk, Wv, bq, bk, bv, Q, K, Vt);
    }

    // 2) P = exp(Q K^T / 8) + partial row sums
    {
        dim3 grid(SEQ / 128, SEQ / 128, BATCH * NHEAD);
        gemm_mma<128, 2><<<grid, 256, SM_G128>>>(Q, K, nullptr, Pattn, PART,
            DHEAD, DEMB, DEMB, SEQ,
            SD, (size_t)DHEAD,
            SD, (size_t)DHEAD,
            (size_t)NHEAD * SS, SS,
            0.125f);
    }

    // 3) row-sum inverse
    reduce_inv<<<NROWS / 256, 256>>>(PART, INV);

    // 4) split-K PV: AOpart[ks] = inv * (P_slice @ Vt_slice^T); P normalized
    {
        dim3 grid(KSPLIT, SEQ / 128, BATCH * NHEAD);
        gemm_pv<<<grid, 256, SM_PV>>>(Pattn, Vt, INV, AOP,
            SEQ, SEQ, DEMB,
            (size_t)NHEAD * SS, SS,
            (size_t)(NHEAD * DHEAD) * SEQ, (size_t)DHEAD * SEQ,
            SD, (size_t)DHEAD);
    }

    // 4b) AO = sum of partials
    reduce_ao<<<(QKV_ELEMS / 4 + 255) / 256, 256>>>(AOP, AO);

    // 5) output = AO @ Wo^T + bo
    {
        dim3 grid(DEMB / 128, (BATCH * SEQ) / 128, 1);
        gemm_mma<128, 0><<<grid, 256, SM_G128>>>(AO, Wo, bo, out, nullptr,
            DEMB, DEMB, DEMB, DEMB, 0,0, 0,0, 0,0, 1.f);
    }
}

// round 17
// speedup vs baseline: 1.0685x; 1.0230x over previous
#include <cuda_runtime.h>
#include <cuda_fp16.h>
#include <cstdint>

// ---------------------------------------------------------------------------
// AttentionLayer: B=2, S1=S2=2048, D=1024, H=16, dh=64
// out layout: [ output (2*2048*1024) | attn_weights (2*16*2048*2048) ] fp32
// mma.sync m16n8k16, fp16 hi/lo split GEMMs, fused exp-softmax with fp16
// unnormalized P scratch; PV reads fp16 P (2-pass MMA) and emits the final
// fp32 normalized attn_weights. Split-K PV (x4).
// ---------------------------------------------------------------------------

#define BATCH 2
#define SEQ   2048
#define DEMB  1024
#define NHEAD 16
#define DHEAD 64

#define QKV_ELEMS (BATCH * SEQ * DEMB)          // 4,194,304
#define NROWS     (BATCH * NHEAD * SEQ)         // 65,536
#define ATTN_OFF  ((size_t)BATCH * SEQ * DEMB)
#define KSPLIT    4
#define KSLICE    (SEQ / KSPLIT)                // 512

__device__ float  g_Q [QKV_ELEMS];
__device__ float  g_K [QKV_ELEMS];
__device__ __half g_Vth[QKV_ELEMS];  // Vt split hi: [(b*1024 + h*64 + d)][s]
__device__ __half g_Vtl[QKV_ELEMS];  // Vt split lo
__device__ float  g_AO[QKV_ELEMS];
__device__ float  g_AOpart[KSPLIT * QKV_ELEMS];
__device__ __half g_Ph[(size_t)NROWS * SEQ];    // unnormalized exp(s), fp16
__device__ float  g_partial[16 * NROWS];
__device__ float  g_inv[NROWS];

// ---------------------------------------------------------------------------
__device__ __forceinline__ void cpasync16(void* dst_smem, const void* src_gmem) {
    uint32_t d = (uint32_t)__cvta_generic_to_shared(dst_smem);
    asm volatile("cp.async.cg.shared.global [%0], [%1], 16;\n" :: "r"(d), "l"(src_gmem));
}
#define CP_COMMIT()  asm volatile("cp.async.commit_group;\n" ::: "memory")
#define CP_WAIT2()   asm volatile("cp.async.wait_group 2;\n" ::: "memory")

__device__ __forceinline__ void cvt2(float2 f, uint32_t& hi, uint32_t& lo) {
    __half2 h = __floats2half2_rn(f.x, f.y);
    float2 hf = __half22float2(h);
    __half2 l = __floats2half2_rn(f.x - hf.x, f.y - hf.y);
    hi = *reinterpret_cast<uint32_t*>(&h);
    lo = *reinterpret_cast<uint32_t*>(&l);
}
__device__ __forceinline__ void split1(float v, __half& h, __half& l) {
    h = __float2half_rn(v);
    l = __float2half_rn(v - __half2float(h));
}
__device__ __forceinline__ void mma16816(float* c, const uint32_t* a, const uint32_t* b) {
    asm volatile(
        "mma.sync.aligned.m16n8k16.row.col.f32.f16.f16.f32 "
        "{%0,%1,%2,%3}, {%4,%5,%6,%7}, {%8,%9}, {%0,%1,%2,%3};\n"
        : "+f"(c[0]), "+f"(c[1]), "+f"(c[2]), "+f"(c[3])
        : "r"(a[0]), "r"(a[1]), "r"(a[2]), "r"(a[3]), "r"(b[0]), "r"(b[1]));
}

// ---------------------------------------------------------------------------
// fp32-operand fragment+3-pass MMA body (projections / scores / out-proj)
// ---------------------------------------------------------------------------
template <int NT>
__device__ __forceinline__ void compute_iter(
    const float (*sAst)[20], const float (*sBst)[20],
    int wm, int wn, int grp, int qid, float acc[][NT][4])
{
    uint32_t aH[4][4], aL[4][4];
#pragma unroll
    for (int mt = 0; mt < 4; mt++) {
        const int r0 = wm + mt * 16 + grp;
        float2 f00 = *reinterpret_cast<const float2*>(&sAst[r0    ][qid * 2    ]);
        float2 f10 = *reinterpret_cast<const float2*>(&sAst[r0 + 8][qid * 2    ]);
        float2 f01 = *reinterpret_cast<const float2*>(&sAst[r0    ][qid * 2 + 8]);
        float2 f11 = *reinterpret_cast<const float2*>(&sAst[r0 + 8][qid * 2 + 8]);
        cvt2(f00, aH[mt][0], aL[mt][0]);
        cvt2(f10, aH[mt][1], aL[mt][1]);
        cvt2(f01, aH[mt][2], aL[mt][2]);
        cvt2(f11, aH[mt][3], aL[mt][3]);
    }
    uint32_t bH[NT][2], bL[NT][2];
#pragma unroll
    for (int nt = 0; nt < NT; nt++) {
        const int c0 = wn + nt * 8 + grp;
        float2 g0 = *reinterpret_cast<const float2*>(&sBst[c0][qid * 2    ]);
        float2 g1 = *reinterpret_cast<const float2*>(&sBst[c0][qid * 2 + 8]);
        cvt2(g0, bH[nt][0], bL[nt][0]);
        cvt2(g1, bH[nt][1], bL[nt][1]);
    }
#pragma unroll
    for (int mt = 0; mt < 4; mt++)
#pragma unroll
        for (int nt = 0; nt < NT; nt++) {
            mma16816(acc[mt][nt], aH[mt], bH[nt]);
            mma16816(acc[mt][nt], aH[mt], bL[nt]);
            mma16816(acc[mt][nt], aL[mt], bH[nt]);
        }
}

// ---------------------------------------------------------------------------
// gemm_mma: 4-stage pipeline. OUTMODE 0: fp32 out (+bias).
// OUTMODE 2: fp16 exp(scale*acc) -> Ph + per-colblock partial row sums.
// ---------------------------------------------------------------------------
template <int BN, int OUTMODE>
__global__ void __launch_bounds__(256)
gemm_mma(const float* __restrict__ A, const float* __restrict__ B,
         const float* __restrict__ bias, float* __restrict__ C,
         __half* __restrict__ Ph, float* __restrict__ partial,
         int K, int lda, int ldb, int ldc,
         size_t aOffB, size_t aOffH,
         size_t bOffB, size_t bOffH,
         size_t cOffB, size_t cOffH,
         float scale)
{
    constexpr int NT = BN / 32;
    extern __shared__ float dsm[];
    float (*sA)[128][20] = reinterpret_cast<float(*)[128][20]>(dsm);
    float (*sB)[BN][20]  = reinterpret_cast<float(*)[BN][20]>(dsm + 4 * 128 * 20);
    float (*sred)[128]   = reinterpret_cast<float(*)[128]>(dsm + 4 * 128 * 20 + 4 * BN * 20);

    const int tid  = threadIdx.x;
    const int wid  = tid >> 5;
    const int lane = tid & 31;
    const int grp  = lane >> 2;
    const int qid  = lane & 3;
    const int wm   = (wid >> 2) * 64;
    const int wn   = (wid & 3) * (BN / 4);

    const int z    = blockIdx.z;
    const int bidx = z >> 4;
    const int h    = z & 15;
    A += (size_t)bidx * aOffB + (size_t)h * aOffH;
    B += (size_t)bidx * bOffB + (size_t)h * bOffH;
    const size_t coff = (size_t)bidx * cOffB + (size_t)h * cOffH;

    const int m0 = blockIdx.y * 128;
    const int n0 = blockIdx.x * BN;
    const float* Ab = A + (size_t)m0 * lda;
    const float* Bb = B + (size_t)n0 * ldb;

    float acc[4][NT][4];
#pragma unroll
    for (int mt = 0; mt < 4; mt++)
#pragma unroll
        for (int nt = 0; nt < NT; nt++)
#pragma unroll
            for (int i = 0; i < 4; i++) acc[mt][nt][i] = 0.f;

    const int NKB = K >> 4;

    auto load_stage = [&](int st, int k0) {
#pragma unroll 2
        for (int i = tid; i < 128 * 4; i += 256) {
            const int r = i >> 2, sgm = i & 3;
            cpasync16(&sA[st][r][sgm * 4], Ab + (size_t)r * lda + k0 + sgm * 4);
        }
#pragma unroll 1
        for (int i = tid; i < BN * 4; i += 256) {
            const int r = i >> 2, sgm = i & 3;
            cpasync16(&sB[st][r][sgm * 4], Bb + (size_t)r * ldb + k0 + sgm * 4);
        }
    };

    load_stage(0, 0);  CP_COMMIT();
    load_stage(1, 16); CP_COMMIT();
    load_stage(2, 32); CP_COMMIT();

    for (int kb = 0; kb < NKB; kb++) {
        CP_WAIT2();
        __syncthreads();
        if (kb + 3 < NKB) load_stage((kb + 3) & 3, (kb + 3) << 4);
        CP_COMMIT();
        compute_iter<NT>(sA[kb & 3], sB[kb & 3], wm, wn, grp, qid, acc);
    }

    if (OUTMODE == 2) {
        __half* Phb = Ph + coff;
        float rs0[4] = {0.f, 0.f, 0.f, 0.f};
        float rs1[4] = {0.f, 0.f, 0.f, 0.f};
#pragma unroll
        for (int mt = 0; mt < 4; mt++) {
#pragma unroll
            for (int nt = 0; nt < NT; nt++) {
                const float* cc = acc[mt][nt];
                const int row = m0 + wm + mt * 16 + grp;
                const int col = n0 + wn + nt * 8 + qid * 2;
                float e00 = __expf(cc[0] * scale);
                float e01 = __expf(cc[1] * scale);
                float e10 = __expf(cc[2] * scale);
                float e11 = __expf(cc[3] * scale);
                rs0[mt] += e00 + e01;
                rs1[mt] += e10 + e11;
                __half2 p0 = __floats2half2_rn(e00, e01);
                __half2 p1 = __floats2half2_rn(e10, e11);
                __stcs(reinterpret_cast<unsigned int*>(&Phb[(size_t)row * ldc + col]),
                       *reinterpret_cast<unsigned int*>(&p0));
                __stcs(reinterpret_cast<unsigned int*>(&Phb[(size_t)(row + 8) * ldc + col]),
                       *reinterpret_cast<unsigned int*>(&p1));
            }
        }
#pragma unroll
        for (int mt = 0; mt < 4; mt++) {
            float s0 = rs0[mt], s1 = rs1[mt];
            s0 += __shfl_xor_sync(0xffffffffu, s0, 1);
            s0 += __shfl_xor_sync(0xffffffffu, s0, 2);
            s1 += __shfl_xor_sync(0xffffffffu, s1, 1);
            s1 += __shfl_xor_sync(0xffffffffu, s1, 2);
            if (qid == 0) {
                sred[wid & 3][wm + mt * 16 + grp]     = s0;
                sred[wid & 3][wm + mt * 16 + grp + 8] = s1;
            }
        }
        __syncthreads();
        if (tid < 128) {
            float p = sred[0][tid] + sred[1][tid] + sred[2][tid] + sred[3][tid];
            partial[(size_t)blockIdx.x * NROWS + (size_t)z * SEQ + m0 + tid] = p;
        }
        return;
    }

    float* Cb = C + coff;
#pragma unroll
    for (int mt = 0; mt < 4; mt++) {
#pragma unroll
        for (int nt = 0; nt < NT; nt++) {
            const float* cc = acc[mt][nt];
            const int row = m0 + wm + mt * 16 + grp;
            const int col = n0 + wn + nt * 8 + qid * 2;
            float b0 = bias ? bias[col]     : 0.f;
            float b1 = bias ? bias[col + 1] : 0.f;
            *reinterpret_cast<float2*>(&Cb[(size_t)row * ldc + col]) =
                make_float2(cc[0] * scale + b0, cc[1] * scale + b1);
            *reinterpret_cast<float2*>(&Cb[(size_t)(row + 8) * ldc + col]) =
                make_float2(cc[2] * scale + b0, cc[3] * scale + b1);
        }
    }
}

// ---------------------------------------------------------------------------
// proj_qkv: merged Q/K/V projections. grid = (8, 32, 3); z selects projection.
// z=2 writes V transposed, split fp16 (Vth/Vtl).
// ---------------------------------------------------------------------------
__global__ void __launch_bounds__(256)
proj_qkv(const float* __restrict__ x1, const float* __restrict__ x2,
         const float* __restrict__ Wq, const float* __restrict__ Wk,
         const float* __restrict__ Wv,
         const float* __restrict__ bq, const float* __restrict__ bk,
         const float* __restrict__ bv,
         float* __restrict__ Qo, float* __restrict__ Ko,
         __half* __restrict__ Vth, __half* __restrict__ Vtl)
{
    constexpr int BN = 128;
    constexpr int NT = 4;
    extern __shared__ float dsm[];
    float (*sA)[128][20] = reinterpret_cast<float(*)[128][20]>(dsm);
    float (*sB)[BN][20]  = reinterpret_cast<float(*)[BN][20]>(dsm + 4 * 128 * 20);

    const int pz = blockIdx.z;
    const float* A    = (pz == 0) ? x1 : x2;
    const float* B    = (pz == 0) ? Wq : (pz == 1 ? Wk : Wv);
    const float* bias = (pz == 0) ? bq : (pz == 1 ? bk : bv);

    const int tid  = threadIdx.x;
    const int wid  = tid >> 5;
    const int lane = tid & 31;
    const int grp  = lane >> 2;
    const int qid  = lane & 3;
    const int wm   = (wid >> 2) * 64;
    const int wn   = (wid & 3) * 32;

    const int m0 = blockIdx.y * 128;
    const int n0 = blockIdx.x * BN;
    const float* Ab = A + (size_t)m0 * DEMB;
    const float* Bb = B + (size_t)n0 * DEMB;

    float acc[4][NT][4];
#pragma unroll
    for (int mt = 0; mt < 4; mt++)
#pragma unroll
        for (int nt = 0; nt < NT; nt++)
#pragma unroll
            for (int i = 0; i < 4; i++) acc[mt][nt][i] = 0.f;

    const int NKB = DEMB >> 4;  // 64

    auto load_stage = [&](int st, int k0) {
#pragma unroll 2
        for (int i = tid; i < 128 * 4; i += 256) {
            const int r = i >> 2, sgm = i & 3;
            cpasync16(&sA[st][r][sgm * 4], Ab + (size_t)r * DEMB + k0 + sgm * 4);
        }
#pragma unroll 2
        for (int i = tid; i < BN * 4; i += 256) {
            const int r = i >> 2, sgm = i & 3;
            cpasync16(&sB[st][r][sgm * 4], Bb + (size_t)r * DEMB + k0 + sgm * 4);
        }
    };

    load_stage(0, 0);  CP_COMMIT();
    load_stage(1, 16); CP_COMMIT();
    load_stage(2, 32); CP_COMMIT();

    for (int kb = 0; kb < NKB; kb++) {
        CP_WAIT2();
        __syncthreads();
        if (kb + 3 < NKB) load_stage((kb + 3) & 3, (kb + 3) << 4);
        CP_COMMIT();
        compute_iter<NT>(sA[kb & 3], sB[kb & 3], wm, wn, grp, qid, acc);
    }

    if (pz < 2) {
        float* C = pz ? Ko : Qo;
#pragma unroll
        for (int mt = 0; mt < 4; mt++) {
#pragma unroll
            for (int nt = 0; nt < NT; nt++) {
                const float* cc = acc[mt][nt];
                const int row = m0 + wm + mt * 16 + grp;
                const int col = n0 + wn + nt * 8 + qid * 2;
                const float b0 = bias[col], b1 = bias[col + 1];
                *reinterpret_cast<float2*>(&C[(size_t)row * DEMB + col]) =
                    make_float2(cc[0] + b0, cc[1] + b1);
                *reinterpret_cast<float2*>(&C[(size_t)(row + 8) * DEMB + col]) =
                    make_float2(cc[2] + b0, cc[3] + b1);
            }
        }
    } else {
#pragma unroll
        for (int mt = 0; mt < 4; mt++) {
#pragma unroll
            for (int nt = 0; nt < NT; nt++) {
                const float* cc = acc[mt][nt];
                const int row = m0 + wm + mt * 16 + grp;
                const int col = n0 + wn + nt * 8 + qid * 2;
                const float b0 = bias[col], b1 = bias[col + 1];
                const int b2 = row >> 11;
                const int s  = row & 2047;
                __half hh, ll;
                size_t p0 = ((size_t)(b2 * 1024 + col)) * 2048 + s;
                size_t p1 = ((size_t)(b2 * 1024 + col + 1)) * 2048 + s;
                split1(cc[0] + b0, hh, ll); Vth[p0] = hh;     Vtl[p0] = ll;
                split1(cc[1] + b1, hh, ll); Vth[p1] = hh;     Vtl[p1] = ll;
                split1(cc[2] + b0, hh, ll); Vth[p0 + 8] = hh; Vtl[p0 + 8] = ll;
                split1(cc[3] + b1, hh, ll); Vth[p1 + 8] = hh; Vtl[p1 + 8] = ll;
            }
        }
    }
}

// ---------------------------------------------------------------------------
__global__ void reduce_inv(const float* __restrict__ partial, float* __restrict__ inv)
{
    const int r = blockIdx.x * blockDim.x + threadIdx.x;
    if (r >= NROWS) return;
    float s = 0.f;
#pragma unroll
    for (int b = 0; b < 16; b++) s += partial[(size_t)b * NROWS + r];
    inv[r] = 1.f / s;
}

// ---------------------------------------------------------------------------
// gemm_pv split-K: A = fp16 Ph (2-pass MMA vs split V), grid (KSPLIT, 16, 32).
// Writes fp32 normalized attn_weights for its k-slice; partial AO -> AOpart.
// ---------------------------------------------------------------------------
__global__ void __launch_bounds__(256)
gemm_pv(const __half* __restrict__ Ph,
        const __half* __restrict__ Bh, const __half* __restrict__ Bl,
        const float* __restrict__ inv,
        float* __restrict__ Pout, float* __restrict__ AOpart)
{
    constexpr int NT = 2;
    extern __shared__ char dsmc[];
    __half (*sAh)[128][24] = reinterpret_cast<__half(*)[128][24]>(dsmc);
    __half (*sBh)[64][24]  = reinterpret_cast<__half(*)[64][24]>(dsmc + 4 * 128 * 24 * 2);
    __half (*sBl)[64][24]  = reinterpret_cast<__half(*)[64][24]>(dsmc + 4 * 128 * 24 * 2 + 4 * 64 * 24 * 2);

    const int tid  = threadIdx.x;
    const int wid  = tid >> 5;
    const int lane = tid & 31;
    const int grp  = lane >> 2;
    const int qid  = lane & 3;
    const int wm   = (wid >> 2) * 64;
    const int wn   = (wid & 3) * 16;

    const int ks   = blockIdx.x;
    const int z    = blockIdx.z;
    const int bidx = z >> 4;
    const int h    = z & 15;
    const size_t SS = (size_t)SEQ * SEQ;
    const size_t SD = (size_t)SEQ * DEMB;

    const int m0 = blockIdx.y * 128;
    const __half* Ab = Ph + (size_t)z * SS + (size_t)m0 * SEQ + ks * KSLICE;
    const __half* Bph = Bh + (size_t)bidx * (NHEAD * DHEAD) * SEQ + (size_t)h * DHEAD * SEQ + ks * KSLICE;
    const __half* Bpl = Bl + (size_t)bidx * (NHEAD * DHEAD) * SEQ + (size_t)h * DHEAD * SEQ + ks * KSLICE;
    float* Pob = Pout + (size_t)z * SS + (size_t)m0 * SEQ + ks * KSLICE;
    float* Cb  = AOpart + (size_t)ks * QKV_ELEMS + (size_t)bidx * SD + (size_t)h * DHEAD;

    const int wbR = tid >> 1;
    const int wbC = (tid & 1) * 8;
    const float wbInv = inv[(size_t)z * SEQ + m0 + wbR];

    float acc[4][NT][4];
#pragma unroll
    for (int mt = 0; mt < 4; mt++)
#pragma unroll
        for (int nt = 0; nt < NT; nt++)
#pragma unroll
            for (int i = 0; i < 4; i++) acc[mt][nt][i] = 0.f;

    const int NKB = KSLICE >> 4;   // 32

    auto load_stage = [&](int st, int k0) {
        {   // A: 128 rows x 16 halves = 2 x 16B chunks per row
            const int r = tid >> 1, c = (tid & 1) * 8;
            cpasync16(&sAh[st][r][c], Ab + (size_t)r * SEQ + k0 + c);
        }
        if (tid < 128) {       // Bh: 64 rows x 2 chunks
            const int r = tid >> 1, c = (tid & 1) * 8;
            cpasync16(&sBh[st][r][c], Bph + (size_t)r * SEQ + k0 + c);
        } else if (tid < 256) {
            const int t = tid - 128;
            const int r = t >> 1, c = (t & 1) * 8;
            cpasync16(&sBl[st][r][c], Bpl + (size_t)r * SEQ + k0 + c);
        }
    };

    load_stage(0, 0);  CP_COMMIT();
    load_stage(1, 16); CP_COMMIT();
    load_stage(2, 32); CP_COMMIT();

    for (int kb = 0; kb < NKB; kb++) {
        CP_WAIT2();
        __syncthreads();
        if (kb + 3 < NKB) load_stage((kb + 3) & 3, (kb + 3) << 4);
        CP_COMMIT();

        const int st = kb & 3;
        const int k0 = kb << 4;

        // normalized fp32 attn_weights writeback from the fp16 tile
        {
            float o[8];
#pragma unroll
            for (int j = 0; j < 8; j += 2) {
                __half2 hv = *reinterpret_cast<const __half2*>(&sAh[st][wbR][wbC + j]);
                float2 fv = __half22float2(hv);
                o[j]     = fv.x * wbInv;
                o[j + 1] = fv.y * wbInv;
            }
            float* dst = Pob + (size_t)wbR * SEQ + k0 + wbC;
            __stcs(reinterpret_cast<float4*>(dst),     make_float4(o[0], o[1], o[2], o[3]));
            __stcs(reinterpret_cast<float4*>(dst + 4), make_float4(o[4], o[5], o[6], o[7]));
        }

        // fragments
        uint32_t aH[4][4];
#pragma unroll
        for (int mt = 0; mt < 4; mt++) {
            const int r0 = wm + mt * 16 + grp;
            aH[mt][0] = *reinterpret_cast<const uint32_t*>(&sAh[st][r0    ][qid * 2    ]);
            aH[mt][1] = *reinterpret_cast<const uint32_t*>(&sAh[st][r0 + 8][qid * 2    ]);
            aH[mt][2] = *reinterpret_cast<const uint32_t*>(&sAh[st][r0    ][qid * 2 + 8]);
            aH[mt][3] = *reinterpret_cast<const uint32_t*>(&sAh[st][r0 + 8][qid * 2 + 8]);
        }
        uint32_t bH[NT][2], bL[NT][2];
#pragma unroll
        for (int nt = 0; nt < NT; nt++) {
            const int c0 = wn + nt * 8 + grp;
            bH[nt][0] = *reinterpret_cast<const uint32_t*>(&sBh[st][c0][qid * 2    ]);
            bH[nt][1] = *reinterpret_cast<const uint32_t*>(&sBh[st][c0][qid * 2 + 8]);
            bL[nt][0] = *reinterpret_cast<const uint32_t*>(&sBl[st][c0][qid * 2    ]);
            bL[nt][1] = *reinterpret_cast<const uint32_t*>(&sBl[st][c0][qid * 2 + 8]);
        }
#pragma unroll
        for (int mt = 0; mt < 4; mt++)
#pragma unroll
            for (int nt = 0; nt < NT; nt++) {
                mma16816(acc[mt][nt], aH[mt], bH[nt]);
                mma16816(acc[mt][nt], aH[mt], bL[nt]);
            }
    }

#pragma unroll
    for (int mt = 0; mt < 4; mt++) {
        const int row = m0 + wm + mt * 16 + grp;
        const float i0 = inv[(size_t)z * SEQ + row];
        const float i1 = inv[(size_t)z * SEQ + row + 8];
#pragma unroll
        for (int nt = 0; nt < NT; nt++) {
            const float* cc = acc[mt][nt];
            const int col = wn + nt * 8 + qid * 2;
            *reinterpret_cast<float2*>(&Cb[(size_t)row * DEMB + col]) =
                make_float2(cc[0] * i0, cc[1] * i0);
            *reinterpret_cast<float2*>(&Cb[(size_t)(row + 8) * DEMB + col]) =
                make_float2(cc[2] * i1, cc[3] * i1);
        }
    }
}

// ---------------------------------------------------------------------------
__global__ void reduce_ao(const float* __restrict__ part, float* __restrict__ AO)
{
    const int i = blockIdx.x * blockDim.x + threadIdx.x;
    if (i >= QKV_ELEMS / 4) return;
    float4 s = reinterpret_cast<const float4*>(part)[i];
#pragma unroll
    for (int b = 1; b < KSPLIT; b++) {
        float4 v = reinterpret_cast<const float4*>(part + (size_t)b * QKV_ELEMS)[i];
        s.x += v.x; s.y += v.y; s.z += v.z; s.w += v.w;
    }
    reinterpret_cast<float4*>(AO)[i] = s;
}

// ---------------------------------------------------------------------------

extern "C" void kernel_launch(void* const* d_in, const int* in_sizes, int n_in,
                              void* d_out, int out_size)
{
    const float* x1 = (const float*)d_in[0];
    const float* x2 = (const float*)d_in[1];
    const float* Wq = (const float*)d_in[2];
    const float* bq = (const float*)d_in[3];
    const float* Wk = (const float*)d_in[4];
    const float* bk = (const float*)d_in[5];
    const float* Wv = (const float*)d_in[6];
    const float* bv = (const float*)d_in[7];
    const float* Wo = (const float*)d_in[8];
    const float* bo = (const float*)d_in[9];
    float* out = (float*)d_out;

    constexpr int SM_G128 = (4 * 128 * 20 + 4 * 128 * 20 + 4 * 128) * 4; // 83968
    constexpr int SM_PROJ = (4 * 128 * 20 + 4 * 128 * 20) * 4;           // 81920
    constexpr int SM_PV   = 4 * 128 * 24 * 2 + 2 * (4 * 64 * 24 * 2);    // 49152

    static float  *Q = nullptr, *K = nullptr, *AO = nullptr,
                  *AOP = nullptr, *PART = nullptr, *INV = nullptr;
    static __half *VTH = nullptr, *VTL = nullptr, *PH = nullptr;
    if (Q == nullptr) {
        cudaGetSymbolAddress((void**)&Q,    g_Q);
        cudaGetSymbolAddress((void**)&K,    g_K);
        cudaGetSymbolAddress((void**)&VTH,  g_Vth);
        cudaGetSymbolAddress((void**)&VTL,  g_Vtl);
        cudaGetSymbolAddress((void**)&AO,   g_AO);
        cudaGetSymbolAddress((void**)&AOP,  g_AOpart);
        cudaGetSymbolAddress((void**)&PH,   g_Ph);
        cudaGetSymbolAddress((void**)&PART, g_partial);
        cudaGetSymbolAddress((void**)&INV,  g_inv);
        cudaFuncSetAttribute(gemm_mma<128, 0>, cudaFuncAttributeMaxDynamicSharedMemorySize, SM_G128);
        cudaFuncSetAttribute(gemm_mma<128, 2>, cudaFuncAttributeMaxDynamicSharedMemorySize, SM_G128);
        cudaFuncSetAttribute(proj_qkv,          cudaFuncAttributeMaxDynamicSharedMemorySize, SM_PROJ);
        cudaFuncSetAttribute(gemm_pv,           cudaFuncAttributeMaxDynamicSharedMemorySize, SM_PV);
    }

    const size_t SD = (size_t)SEQ * DEMB;   // 2,097,152
    const size_t SS = (size_t)SEQ * SEQ;    // 4,194,304
    float* Pattn = out + ATTN_OFF;

    // 1) merged Q/K/V projections (V -> transposed split fp16)
    {
        dim3 grid(DEMB / 128, (BATCH * SEQ) / 128, 3);
        proj_qkv<<<grid, 256, SM_PROJ>>>(x1, x2, Wq, Wk, Wv, bq, bk, bv, Q, K, VTH, VTL);
    }

    // 2) Ph = fp16 exp(Q K^T / 8) + partial row sums
    {
        dim3 grid(SEQ / 128, SEQ / 128, BATCH * NHEAD);
        gemm_mma<128, 2><<<grid, 256, SM_G128>>>(Q, K, nullptr, nullptr, PH, PART,
            DHEAD, DEMB, DEMB, SEQ,
            SD, (size_t)DHEAD,
            SD, (size_t)DHEAD,
            (size_t)NHEAD * SS, SS,
            0.125f);
    }

    // 3) row-sum inverse
    reduce_inv<<<NROWS / 256, 256>>>(PART, INV);

    // 4) split-K PV: AOpart = inv * (Ph @ Vt^T); fp32 normalized attn -> d_out
    {
        dim3 grid(KSPLIT, SEQ / 128, BATCH * NHEAD);
        gemm_pv<<<grid, 256, SM_PV>>>(PH, VTH, VTL, INV, Pattn, AOP);
    }

    // 4b) AO = sum of partials
    reduce_ao<<<(QKV_ELEMS / 4 + 255) / 256, 256>>>(AOP, AO);

    // 5) output = AO @ Wo^T + bo
    {
        dim3 grid(DEMB / 128, (BATCH * SEQ) / 128, 1);
        gemm_mma<128, 0><<<grid, 256, SM_G128>>>(AO, Wo, bo, out, nullptr, nullptr,
            DEMB, DEMB, DEMB, DEMB, 0,0, 0,0, 0,0, 1.f);
    }
}